// round 5
// baseline (speedup 1.0000x reference)
#include <cuda_runtime.h>
#include <cuda_bf16.h>
#include <cstdint>

namespace {

constexpr int kS  = 2048;
constexpr int kD  = 64;
constexpr int kBH = 32;
constexpr int kNE = kBH * kS * kD;        // 4,194,304 elements per tensor

// split-bf16 scratch planes (static __device__ = allowed scratch)
__device__ __align__(16) __nv_bfloat16 g_qh[kNE];
__device__ __align__(16) __nv_bfloat16 g_ql[kNE];
__device__ __align__(16) __nv_bfloat16 g_kh[kNE];
__device__ __align__(16) __nv_bfloat16 g_kl[kNE];
__device__ __align__(16) __nv_bfloat16 g_vh[kNE];
__device__ __align__(16) __nv_bfloat16 g_vl[kNE];

// smem: 6 x 16KB tile slots = 96KB. Pass 1 reuses KH/KL slots as a KH double buffer.
constexpr int SM_QH = 0;
constexpr int SM_QL = 16384;
constexpr int SM_KH = 32768;
constexpr int SM_KL = 49152;
constexpr int SM_VH = 65536;
constexpr int SM_VL = 81920;
constexpr int SM_TOTAL = 98304;

__device__ __forceinline__ uint32_t cvta_sm(const void* p) {
    uint32_t a;
    asm("{ .reg .u64 t; cvta.to.shared.u64 t, %1; cvt.u32.u64 %0, t; }" : "=r"(a) : "l"(p));
    return a;
}

#define CP_COMMIT() asm volatile("cp.async.commit_group;" ::: "memory")
#define CP_WAIT(N)  asm volatile("cp.async.wait_group %0;" :: "n"(N) : "memory")

__device__ __forceinline__ void cp16(uint32_t dst, const void* src) {
    asm volatile("cp.async.cg.shared.global [%0], [%1], 16;" :: "r"(dst), "l"(src) : "memory");
}

// async-copy one [128 x 128B] tile (1024 uint4) into XOR-swizzled smem
__device__ __forceinline__ void fill_async(uint32_t smdst, const uint4* __restrict__ src, int tid) {
#pragma unroll
    for (int i = tid; i < 1024; i += 256) {
        int r = i >> 3, c = i & 7;
        cp16(smdst + r * 128 + ((c ^ (r & 7)) << 4), src + i);
    }
}

__device__ __forceinline__ void ldsm4(uint32_t* r, uint32_t a) {
    asm volatile("ldmatrix.sync.aligned.m8n8.x4.shared.b16 {%0,%1,%2,%3}, [%4];"
                 : "=r"(r[0]), "=r"(r[1]), "=r"(r[2]), "=r"(r[3]) : "r"(a));
}
__device__ __forceinline__ void ldsm4t(uint32_t* r, uint32_t a) {
    asm volatile("ldmatrix.sync.aligned.m8n8.x4.trans.shared.b16 {%0,%1,%2,%3}, [%4];"
                 : "=r"(r[0]), "=r"(r[1]), "=r"(r[2]), "=r"(r[3]) : "r"(a));
}

__device__ __forceinline__ void mma16816(float* d, const uint32_t* a, uint32_t b0, uint32_t b1) {
    asm volatile(
        "mma.sync.aligned.m16n8k16.row.col.f32.bf16.bf16.f32 "
        "{%0,%1,%2,%3}, {%4,%5,%6,%7}, {%8,%9}, {%0,%1,%2,%3};"
        : "+f"(d[0]), "+f"(d[1]), "+f"(d[2]), "+f"(d[3])
        : "r"(a[0]), "r"(a[1]), "r"(a[2]), "r"(a[3]), "r"(b0), "r"(b1));
}

__device__ __forceinline__ uint32_t frag_addr(uint32_t tile, int row0, int c16, int lane) {
    int r = row0 + (lane & 15);
    int c = c16 + (lane >> 4);
    return tile + r * 128 + ((c ^ (r & 7)) << 4);
}

__device__ __forceinline__ void split2(float a, float b, uint32_t& hi, uint32_t& lo) {
    __nv_bfloat162 h = __floats2bfloat162_rn(a, b);
    __nv_bfloat162 l = __floats2bfloat162_rn(a - __bfloat162float(h.x),
                                             b - __bfloat162float(h.y));
    hi = *reinterpret_cast<uint32_t*>(&h);
    lo = *reinterpret_cast<uint32_t*>(&l);
}

// pass-1 QK: 2 products (qh+ql)*kh over cols [cloc, cloc+64)
__device__ __forceinline__ void qk2_chunk(float* S, uint32_t smQh, uint32_t smQl,
                                          uint32_t smKh, int warp, int cloc, int lane) {
#pragma unroll
    for (int i = 0; i < 32; i++) S[i] = 0.f;
#pragma unroll
    for (int kk = 0; kk < 4; kk++) {
        uint32_t qh[4], ql[4];
        ldsm4(qh, frag_addr(smQh, warp * 16, 2 * kk, lane));
        ldsm4(ql, frag_addr(smQl, warp * 16, 2 * kk, lane));
#pragma unroll
        for (int g2 = 0; g2 < 4; g2++) {
            uint32_t kh[4];
            ldsm4(kh, frag_addr(smKh, cloc + g2 * 16, 2 * kk, lane));
            float* s0 = S + g2 * 8;
            float* s1 = S + g2 * 8 + 4;
            mma16816(s0, qh, kh[0], kh[2]);
            mma16816(s0, ql, kh[0], kh[2]);
            mma16816(s1, qh, kh[1], kh[3]);
            mma16816(s1, ql, kh[1], kh[3]);
        }
    }
}

// pass-2 QK: full 3-product split
__device__ __forceinline__ void qk3_chunk(float* S, uint32_t smQh, uint32_t smQl,
                                          uint32_t smKh, uint32_t smKl,
                                          int warp, int cloc, int lane) {
#pragma unroll
    for (int i = 0; i < 32; i++) S[i] = 0.f;
#pragma unroll
    for (int kk = 0; kk < 4; kk++) {
        uint32_t qh[4], ql[4];
        ldsm4(qh, frag_addr(smQh, warp * 16, 2 * kk, lane));
        ldsm4(ql, frag_addr(smQl, warp * 16, 2 * kk, lane));
#pragma unroll
        for (int g2 = 0; g2 < 4; g2++) {
            uint32_t kh[4], kl[4];
            ldsm4(kh, frag_addr(smKh, cloc + g2 * 16, 2 * kk, lane));
            ldsm4(kl, frag_addr(smKl, cloc + g2 * 16, 2 * kk, lane));
            float* s0 = S + g2 * 8;
            float* s1 = S + g2 * 8 + 4;
            mma16816(s0, qh, kh[0], kh[2]);
            mma16816(s0, qh, kl[0], kl[2]);
            mma16816(s0, ql, kh[0], kh[2]);
            mma16816(s1, qh, kh[1], kh[3]);
            mma16816(s1, qh, kl[1], kl[3]);
            mma16816(s1, ql, kh[1], kh[3]);
        }
    }
}

__device__ __forceinline__ void pv_chunk(float* O, const float* P,
                                         uint32_t smVh, uint32_t smVl,
                                         int cloc, int lane) {
#pragma unroll
    for (int kk = 0; kk < 4; kk++) {
        const float* p = P + kk * 8;
        uint32_t ah[4], al[4];
        split2(p[0], p[1], ah[0], al[0]);
        split2(p[2], p[3], ah[1], al[1]);
        split2(p[4], p[5], ah[2], al[2]);
        split2(p[6], p[7], ah[3], al[3]);
#pragma unroll
        for (int g2 = 0; g2 < 4; g2++) {
            uint32_t vh[4], vl[4];
            ldsm4t(vh, frag_addr(smVh, cloc + kk * 16, 2 * g2, lane));
            ldsm4t(vl, frag_addr(smVl, cloc + kk * 16, 2 * g2, lane));
            float* o0 = O + g2 * 8;
            float* o1 = O + g2 * 8 + 4;
            mma16816(o0, ah, vh[0], vh[1]);
            mma16816(o0, ah, vl[0], vl[1]);
            mma16816(o0, al, vh[0], vh[1]);
            mma16816(o1, ah, vh[2], vh[3]);
            mma16816(o1, ah, vl[2], vl[3]);
            mma16816(o1, al, vh[2], vh[3]);
        }
    }
}

__global__ void split_kernel(const float4* __restrict__ Q, const float4* __restrict__ K,
                             const float4* __restrict__ V, int n4) {
    uint2* qh = reinterpret_cast<uint2*>(g_qh);
    uint2* ql = reinterpret_cast<uint2*>(g_ql);
    uint2* kh = reinterpret_cast<uint2*>(g_kh);
    uint2* kl = reinterpret_cast<uint2*>(g_kl);
    uint2* vh = reinterpret_cast<uint2*>(g_vh);
    uint2* vl = reinterpret_cast<uint2*>(g_vl);
    for (int i = blockIdx.x * blockDim.x + threadIdx.x; i < n4; i += gridDim.x * blockDim.x) {
        float4 q = Q[i];
        uint32_t h0, l0, h1, l1;
        split2(q.x * 0.125f, q.y * 0.125f, h0, l0);
        split2(q.z * 0.125f, q.w * 0.125f, h1, l1);
        qh[i] = make_uint2(h0, h1); ql[i] = make_uint2(l0, l1);
        float4 k = K[i];
        split2(k.x, k.y, h0, l0);
        split2(k.z, k.w, h1, l1);
        kh[i] = make_uint2(h0, h1); kl[i] = make_uint2(l0, l1);
        float4 v = V[i];
        split2(v.x, v.y, h0, l0);
        split2(v.z, v.w, h1, l1);
        vh[i] = make_uint2(h0, h1); vl[i] = make_uint2(l0, l1);
    }
}

__global__ void __launch_bounds__(256, 2)
attn_main(float* __restrict__ Og, float* __restrict__ Wg) {
    extern __shared__ char smb[];
    const uint32_t sb = cvta_sm(smb);
    const int tid  = threadIdx.x;
    const int warp = tid >> 5;
    const int lane = tid & 31;

    const int qt  = (gridDim.x - 1) - blockIdx.x;   // heavy tiles first
    const int bh  = blockIdx.y;
    const int nkt = qt + 1;

    float* wbase = Wg + ((size_t)bh * kS + (size_t)qt * 128) * kS;

    // zero strictly-masked columns [nkt*128, S) with evict-first stores
    {
        int c0 = nkt * 128;
        if (c0 < kS) {
            int per_row = (kS - c0) >> 2;
            int total   = 128 * per_row;
            float4 z = make_float4(0.f, 0.f, 0.f, 0.f);
            for (int i = tid; i < total; i += 256) {
                int r = i / per_row, c = i - r * per_row;
                __stcs(reinterpret_cast<float4*>(wbase + (size_t)r * kS + c0) + c, z);
            }
        }
    }

    const size_t qtb = ((size_t)bh * kS + (size_t)qt * 128) * kD / 8;   // uint4 index

    // stage Q tile (hi/lo) once + pass-1 K[0]
    fill_async(sb + SM_QH, reinterpret_cast<const uint4*>(g_qh) + qtb, tid);
    fill_async(sb + SM_QL, reinterpret_cast<const uint4*>(g_ql) + qtb, tid);
    {
        size_t tb = ((size_t)bh * kS) * kD / 8;
        fill_async(sb + SM_KH, reinterpret_cast<const uint4*>(g_kh) + tb, tid);
    }
    CP_COMMIT();

    const int rowloc = warp * 16 + (lane >> 2);   // local q-row (lo); +8 for hi
    const int colb   = (lane & 3) * 2;

    // =================== PASS 1: row sums (2-product QK, KH only, dbl-buffered) ==========
    float sum_lo = 0.f, sum_hi = 0.f;
    for (int kt = 0; kt < nkt; kt++) {
        CP_WAIT(0);
        __syncthreads();
        const uint32_t kbuf = sb + ((kt & 1) ? SM_KL : SM_KH);
        if (kt + 1 < nkt) {
            size_t tb = ((size_t)bh * kS + (size_t)(kt + 1) * 128) * kD / 8;
            fill_async(sb + (((kt + 1) & 1) ? SM_KL : SM_KH),
                       reinterpret_cast<const uint4*>(g_kh) + tb, tid);
            CP_COMMIT();
        }
        const bool diag = (kt == qt);
#pragma unroll
        for (int c = 0; c < 2; c++) {
            if (diag && c * 64 > warp * 16 + 15) continue;   // fully masked
            float S[32];
            qk2_chunk(S, sb + SM_QH, sb + SM_QL, kbuf, warp, c * 64, lane);
#pragma unroll
            for (int f = 0; f < 8; f++) {
                int c0 = c * 64 + f * 8 + colb;
                float e0 = __expf(S[4 * f + 0]);
                float e1 = __expf(S[4 * f + 1]);
                float e2 = __expf(S[4 * f + 2]);
                float e3 = __expf(S[4 * f + 3]);
                if (diag) {
                    if (c0     > rowloc)     e0 = 0.f;
                    if (c0 + 1 > rowloc)     e1 = 0.f;
                    if (c0     > rowloc + 8) e2 = 0.f;
                    if (c0 + 1 > rowloc + 8) e3 = 0.f;
                }
                sum_lo += e0 + e1;
                sum_hi += e2 + e3;
            }
        }
    }
    sum_lo += __shfl_xor_sync(0xffffffffu, sum_lo, 1);
    sum_lo += __shfl_xor_sync(0xffffffffu, sum_lo, 2);
    sum_hi += __shfl_xor_sync(0xffffffffu, sum_hi, 1);
    sum_hi += __shfl_xor_sync(0xffffffffu, sum_hi, 2);
    const float rl_lo = 1.0f / sum_lo;
    const float rl_hi = 1.0f / sum_hi;

    __syncthreads();   // pass-1 reads done before pass-2 refills K slots

    // prologue pass 2: K[0] then V[0] as separate groups
    {
        size_t tb = ((size_t)bh * kS) * kD / 8;
        fill_async(sb + SM_KH, reinterpret_cast<const uint4*>(g_kh) + tb, tid);
        fill_async(sb + SM_KL, reinterpret_cast<const uint4*>(g_kl) + tb, tid);
        CP_COMMIT();
        fill_async(sb + SM_VH, reinterpret_cast<const uint4*>(g_vh) + tb, tid);
        fill_async(sb + SM_VL, reinterpret_cast<const uint4*>(g_vl) + tb, tid);
        CP_COMMIT();
    }

    // =================== PASS 2: weights + P@V (staggered K/V pipelining) ===============
    float O[32];
#pragma unroll
    for (int i = 0; i < 32; i++) O[i] = 0.f;

    for (int kt = 0; kt < nkt; kt++) {
        CP_WAIT(1);         // K[kt] resident (V[kt] may still fly)
        __syncthreads();
        const bool diag = (kt == qt);
        const bool pre  = (kt + 1 < nkt);
        float* wlo = wbase + (size_t)rowloc * kS + kt * 128;
        float* whi = wlo + (size_t)8 * kS;

        // QK for both 64-col chunks first (K buffer freed before refill)
        float S0[32], S1[32];
        {
            const bool skip1 = diag && (64 > warp * 16 + 15);
            qk3_chunk(S0, sb + SM_QH, sb + SM_QL, sb + SM_KH, sb + SM_KL, warp, 0, lane);
            if (!skip1)
                qk3_chunk(S1, sb + SM_QH, sb + SM_QL, sb + SM_KH, sb + SM_KL, warp, 64, lane);
            else
#pragma unroll
                for (int i = 0; i < 32; i++) S1[i] = 0.f;
        }
        __syncthreads();    // all warps done reading K
        if (pre) {          // prefetch K[kt+1]; hides behind epilogue + PV
            size_t tb = ((size_t)bh * kS + (size_t)(kt + 1) * 128) * kD / 8;
            fill_async(sb + SM_KH, reinterpret_cast<const uint4*>(g_kh) + tb, tid);
            fill_async(sb + SM_KL, reinterpret_cast<const uint4*>(g_kl) + tb, tid);
            CP_COMMIT();
        }

        // epilogue: exp, normalize, mask, store W
#pragma unroll
        for (int c = 0; c < 2; c++) {
            float* S = c ? S1 : S0;
            const bool skip = diag && (c * 64 > warp * 16 + 15);
#pragma unroll
            for (int f = 0; f < 8; f++) {
                int c0 = c * 64 + f * 8 + colb;
                float e0, e1, e2, e3;
                if (skip) {
                    e0 = e1 = e2 = e3 = 0.f;
                } else {
                    e0 = __expf(S[4 * f + 0]) * rl_lo;
                    e1 = __expf(S[4 * f + 1]) * rl_lo;
                    e2 = __expf(S[4 * f + 2]) * rl_hi;
                    e3 = __expf(S[4 * f + 3]) * rl_hi;
                    if (diag) {
                        if (c0     > rowloc)     e0 = 0.f;
                        if (c0 + 1 > rowloc)     e1 = 0.f;
                        if (c0     > rowloc + 8) e2 = 0.f;
                        if (c0 + 1 > rowloc + 8) e3 = 0.f;
                    }
                }
                __stcs(reinterpret_cast<float2*>(wlo + c0), make_float2(e0, e1));
                __stcs(reinterpret_cast<float2*>(whi + c0), make_float2(e2, e3));
                S[4 * f + 0] = e0; S[4 * f + 1] = e1;
                S[4 * f + 2] = e2; S[4 * f + 3] = e3;
            }
        }

        // V[kt] must be resident; K[kt+1] may still fly
        if (pre) CP_WAIT(1); else CP_WAIT(0);
        __syncthreads();

        {
            const bool skip1 = diag && (64 > warp * 16 + 15);
            pv_chunk(O, S0, sb + SM_VH, sb + SM_VL, 0, lane);
            if (!skip1)
                pv_chunk(O, S1, sb + SM_VH, sb + SM_VL, 64, lane);
        }
        __syncthreads();    // all warps done reading V
        if (pre) {          // prefetch V[kt+1]; hides behind next iter's QK + epilogue
            size_t tb = ((size_t)bh * kS + (size_t)(kt + 1) * 128) * kD / 8;
            fill_async(sb + SM_VH, reinterpret_cast<const uint4*>(g_vh) + tb, tid);
            fill_async(sb + SM_VL, reinterpret_cast<const uint4*>(g_vl) + tb, tid);
            CP_COMMIT();
        }
    }

    // write O
    {
        float* olo = Og + ((size_t)bh * kS + (size_t)qt * 128 + rowloc) * kD;
        float* ohi = olo + (size_t)8 * kD;
#pragma unroll
        for (int f = 0; f < 8; f++) {
            int d0 = f * 8 + colb;
            *reinterpret_cast<float2*>(olo + d0) = make_float2(O[4 * f + 0], O[4 * f + 1]);
            *reinterpret_cast<float2*>(ohi + d0) = make_float2(O[4 * f + 2], O[4 * f + 3]);
        }
    }
}

} // namespace

extern "C" void kernel_launch(void* const* d_in, const int* in_sizes, int n_in,
                              void* d_out, int out_size) {
    const float* Q = (const float*)d_in[0];
    const float* K = (const float*)d_in[1];
    const float* V = (const float*)d_in[2];
    (void)in_sizes; (void)n_in; (void)out_size;   // d_in[3] = tril mask, applied analytically

    float* out = (float*)d_out;                   // [B,H,S,D]
    float* w   = out + (size_t)kBH * kS * kD;     // [B,H,S,S]

    static bool attr_set = false;
    if (!attr_set) {
        cudaFuncSetAttribute(attn_main, cudaFuncAttributeMaxDynamicSharedMemorySize, SM_TOTAL);
        attr_set = true;
    }

    split_kernel<<<2048, 256>>>((const float4*)Q, (const float4*)K, (const float4*)V, kNE / 4);
    dim3 grid(kS / 128, kBH);
    attn_main<<<grid, 256, SM_TOTAL>>>(out, w);
}